// round 15
// baseline (speedup 1.0000x reference)
#include <cuda_runtime.h>

#define NSEG 16384
#define DFEAT 128
#define EPSV 1e-10f
#define RPW 64                  // rows per warp (pool kernel)
#define RB 8                    // row batch (ILP depth)
#define SEGB 64                 // segments per block (gemm kernel)
#define KP 32                   // k-panel rows (gemm kernel)
#define GT 128                  // gemm threads per block

// Scratch (allocation-free requirement -> __device__ globals).
// Zero-initialized at module load; out_gemm_kernel re-zeros its own slice
// (pure stores, after compute) so every call sees zeroed scratch.
__device__ float g_pooled[NSEG * DFEAT];   // 8 MB
__device__ float g_denom[NSEG];

__device__ __forceinline__ float4 ldcs4(const float4* p) {
    return __ldcs(p);           // evict-first streaming load
}

// ---------------------------------------------------------------------------
// Kernel 1: fused gate + weighted segment pooling (frozen; ~7 TB/s).
// ---------------------------------------------------------------------------
__global__ void __launch_bounds__(256) gate_pool_kernel(
    const float4* __restrict__ x4,        // [N, 32] float4 view of [N,128]
    const int*    __restrict__ index,     // [N] sorted
    const float*  __restrict__ weights,   // [N]
    const float*  __restrict__ gate_w,    // [128]
    const float*  __restrict__ gate_b,    // [1]
    const float*  __restrict__ pow_p,     // [1]
    int n_rows)
{
    const int lane = threadIdx.x & 31;
    const int warp_global = (blockIdx.x * blockDim.x + threadIdx.x) >> 5;
    const int row0 = warp_global * RPW;
    if (row0 >= n_rows) return;
    const int row_end = min(n_rows, row0 + RPW);

    const float4 gw = reinterpret_cast<const float4*>(gate_w)[lane];
    const float gb = __ldg(gate_b);
    const float p  = __ldg(pow_p);

    const int jmine = 4 * ((lane >> 2) & 1) + 2 * ((lane >> 3) & 1) + ((lane >> 4) & 1);
    const int SRC[RB] = {0, 16, 8, 24, 4, 20, 12, 28};

    float4 acc = make_float4(0.f, 0.f, 0.f, 0.f);
    float dsum = 0.f;
    int cur = __ldg(&index[row0]);

    auto flush = [&]() {
        float* dst = &g_pooled[cur * DFEAT + lane * 4];
        atomicAdd(dst + 0, acc.x);
        atomicAdd(dst + 1, acc.y);
        atomicAdd(dst + 2, acc.z);
        atomicAdd(dst + 3, acc.w);
        if (lane == 0) atomicAdd(&g_denom[cur], dsum);
        acc = make_float4(0.f, 0.f, 0.f, 0.f);
        dsum = 0.f;
    };

    int r = row0;
    for (; r + RB <= row_end; r += RB) {
        float4 xv[RB];
        #pragma unroll
        for (int j = 0; j < RB; ++j)
            xv[j] = ldcs4(&x4[(size_t)(r + j) * 32 + lane]);
        const int segLast = __ldg(&index[r + RB - 1]);
        const float wmine = __ldg(&weights[r + jmine]);

        float pt[RB];
        #pragma unroll
        for (int j = 0; j < RB; ++j)
            pt[j] = xv[j].x * gw.x + xv[j].y * gw.y
                  + xv[j].z * gw.z + xv[j].w * gw.w;

        float q[4];
        #pragma unroll
        for (int k = 0; k < 4; ++k) {
            const float t0 = pt[2 * k]     + __shfl_xor_sync(0xffffffffu, pt[2 * k], 16);
            const float t1 = pt[2 * k + 1] + __shfl_xor_sync(0xffffffffu, pt[2 * k + 1], 16);
            q[k] = (lane & 16) ? t1 : t0;
        }
        float rr2[2];
        #pragma unroll
        for (int m = 0; m < 2; ++m) {
            const float t0 = q[2 * m]     + __shfl_xor_sync(0xffffffffu, q[2 * m], 8);
            const float t1 = q[2 * m + 1] + __shfl_xor_sync(0xffffffffu, q[2 * m + 1], 8);
            rr2[m] = (lane & 8) ? t1 : t0;
        }
        float s;
        {
            const float t0 = rr2[0] + __shfl_xor_sync(0xffffffffu, rr2[0], 4);
            const float t1 = rr2[1] + __shfl_xor_sync(0xffffffffu, rr2[1], 4);
            s = (lane & 4) ? t1 : t0;
        }
        s += __shfl_xor_sync(0xffffffffu, s, 2);
        s += __shfl_xor_sync(0xffffffffu, s, 1);

        const float emine = __expf(__fmaf_rn(p, __logf(wmine), s + gb));

        float e[RB];
        #pragma unroll
        for (int j = 0; j < RB; ++j)
            e[j] = __shfl_sync(0xffffffffu, emine, SRC[j]);

        if (segLast == cur) {
            #pragma unroll
            for (int j = 0; j < RB; ++j) {
                acc.x += e[j] * xv[j].x;
                acc.y += e[j] * xv[j].y;
                acc.z += e[j] * xv[j].z;
                acc.w += e[j] * xv[j].w;
                dsum  += e[j];
            }
        } else {
            #pragma unroll
            for (int j = 0; j < RB; ++j) {
                const int seg = __ldg(&index[r + j]);
                if (seg != cur) { flush(); cur = seg; }
                acc.x += e[j] * xv[j].x;
                acc.y += e[j] * xv[j].y;
                acc.z += e[j] * xv[j].z;
                acc.w += e[j] * xv[j].w;
                dsum  += e[j];
            }
        }
    }
    for (; r < row_end; ++r) {
        const int seg = __ldg(&index[r]);
        const float4 xv = ldcs4(&x4[(size_t)r * 32 + lane]);
        const float w = __ldg(&weights[r]);
        float part = xv.x * gw.x + xv.y * gw.y + xv.z * gw.z + xv.w * gw.w;
        #pragma unroll
        for (int off = 16; off; off >>= 1)
            part += __shfl_xor_sync(0xffffffffu, part, off);
        const float e = __expf(__fmaf_rn(p, __logf(w), part + gb));
        if (seg != cur) { flush(); cur = seg; }
        acc.x += e * xv.x;
        acc.y += e * xv.y;
        acc.z += e * xv.z;
        acc.w += e * xv.w;
        dsum += e;
    }
    flush();
}

// ---------------------------------------------------------------------------
// Kernel 2: smem-blocked GEMM epilogue, 8-seg x 8-col register tiles.
// 128 threads = 16 col-groups (8 cols each) x 8 seg-groups (8 segs each);
// SEGB=64 segs/block (256 blocks), KP=32 k-panel. pr 32KB + mw 16KB = 48KB
// static. Per k-step the crossbar traffic is ~1B/FFMA (vs 2 before), so the
// kernel is FFMA-bound with ~5x crossbar margin instead of co-saturated.
// Tail re-zeros this block's scratch slice (pure stores).
// ---------------------------------------------------------------------------
__global__ void __launch_bounds__(GT) out_gemm_kernel(
    const float* __restrict__ msg_w,      // [128,128] row-major (k, n)
    const float* __restrict__ msg_b,      // [128]
    float*       __restrict__ out)        // [NSEG,128]
{
    __shared__ float pr[SEGB][DFEAT];     // 32 KB (normalized pooled rows)
    __shared__ float mw[KP][DFEAT];       // 16 KB (k-panel; row 0 = den scratch)

    const int s0 = blockIdx.x * SEGB;
    const int tid = threadIdx.x;
    const int cg = tid & 15;              // 8 cols at cg*8
    const int sg = tid >> 4;              // 8 segs at sg*8

    // stage 1: den -> mw[0][0..63]
    if (tid < SEGB) mw[0][tid] = g_denom[s0 + tid];
    __syncthreads();

    // per-thread bias gains for my 8 segments (registers, before mw reuse)
    float gbias[8];
    #pragma unroll
    for (int i = 0; i < 8; ++i) {
        const float den = mw[0][sg * 8 + i];
        gbias[i] = den / (den + EPSV);
    }

    // stage 2: build normalized pr = pooled / (den + eps); 2048 float4s
    {
        const float4* gp4 = reinterpret_cast<const float4*>(g_pooled) + (size_t)s0 * 32;
        #pragma unroll
        for (int j = 0; j < 16; ++j) {
            const int idx = tid + j * GT;           // 0..2047
            const int rr = idx >> 5;
            const int cc = idx & 31;
            const float inv = __frcp_rn(mw[0][rr] + EPSV);
            const float4 v = gp4[idx];
            *reinterpret_cast<float4*>(&pr[rr][cc * 4]) =
                make_float4(v.x * inv, v.y * inv, v.z * inv, v.w * inv);
        }
    }

    float4 acc0[8], acc1[8];
    #pragma unroll
    for (int i = 0; i < 8; ++i) {
        acc0[i] = make_float4(0.f, 0.f, 0.f, 0.f);
        acc1[i] = make_float4(0.f, 0.f, 0.f, 0.f);
    }

    #pragma unroll
    for (int pnl = 0; pnl < DFEAT / KP; ++pnl) {
        __syncthreads();   // pr built / previous panel consumed / den scratch done
        // load k-panel: 32x128 floats = 1024 float4, 8 per thread, coalesced
        {
            const float4* src = reinterpret_cast<const float4*>(msg_w) + pnl * KP * 32;
            #pragma unroll
            for (int j = 0; j < 8; ++j) {
                const int idx = tid + j * GT;       // 0..1023
                *reinterpret_cast<float4*>(&mw[idx >> 5][(idx & 31) * 4]) = src[idx];
            }
        }
        __syncthreads();

        // compute: k in steps of 4; 8 segs x 8 cols per thread
        #pragma unroll
        for (int kk = 0; kk < KP; kk += 4) {
            float4 m0[4], m1[4];
            #pragma unroll
            for (int t = 0; t < 4; ++t) {
                m0[t] = *reinterpret_cast<const float4*>(&mw[kk + t][cg * 8]);
                m1[t] = *reinterpret_cast<const float4*>(&mw[kk + t][cg * 8 + 4]);
            }
            const int k = pnl * KP + kk;
            #pragma unroll
            for (int i = 0; i < 8; ++i) {
                const float4 pv = *reinterpret_cast<const float4*>(&pr[sg * 8 + i][k]);
                acc0[i].x += pv.x * m0[0].x; acc0[i].y += pv.x * m0[0].y;
                acc0[i].z += pv.x * m0[0].z; acc0[i].w += pv.x * m0[0].w;
                acc1[i].x += pv.x * m1[0].x; acc1[i].y += pv.x * m1[0].y;
                acc1[i].z += pv.x * m1[0].z; acc1[i].w += pv.x * m1[0].w;

                acc0[i].x += pv.y * m0[1].x; acc0[i].y += pv.y * m0[1].y;
                acc0[i].z += pv.y * m0[1].z; acc0[i].w += pv.y * m0[1].w;
                acc1[i].x += pv.y * m1[1].x; acc1[i].y += pv.y * m1[1].y;
                acc1[i].z += pv.y * m1[1].z; acc1[i].w += pv.y * m1[1].w;

                acc0[i].x += pv.z * m0[2].x; acc0[i].y += pv.z * m0[2].y;
                acc0[i].z += pv.z * m0[2].z; acc0[i].w += pv.z * m0[2].w;
                acc1[i].x += pv.z * m1[2].x; acc1[i].y += pv.z * m1[2].y;
                acc1[i].z += pv.z * m1[2].z; acc1[i].w += pv.z * m1[2].w;

                acc0[i].x += pv.w * m0[3].x; acc0[i].y += pv.w * m0[3].y;
                acc0[i].z += pv.w * m0[3].z; acc0[i].w += pv.w * m0[3].w;
                acc1[i].x += pv.w * m1[3].x; acc1[i].y += pv.w * m1[3].y;
                acc1[i].z += pv.w * m1[3].z; acc1[i].w += pv.w * m1[3].w;
            }
        }
    }

    // epilogue: + g * msg_b, write out (2 float4 per seg per thread)
    const float4 mb0 = reinterpret_cast<const float4*>(msg_b)[cg * 2];
    const float4 mb1 = reinterpret_cast<const float4*>(msg_b)[cg * 2 + 1];
    #pragma unroll
    for (int i = 0; i < 8; ++i) {
        const int seg = s0 + sg * 8 + i;
        float4 o0 = make_float4(acc0[i].x + gbias[i] * mb0.x,
                                acc0[i].y + gbias[i] * mb0.y,
                                acc0[i].z + gbias[i] * mb0.z,
                                acc0[i].w + gbias[i] * mb0.w);
        float4 o1 = make_float4(acc1[i].x + gbias[i] * mb1.x,
                                acc1[i].y + gbias[i] * mb1.y,
                                acc1[i].z + gbias[i] * mb1.z,
                                acc1[i].w + gbias[i] * mb1.w);
        reinterpret_cast<float4*>(out)[(size_t)seg * 32 + cg * 2]     = o0;
        reinterpret_cast<float4*>(out)[(size_t)seg * 32 + cg * 2 + 1] = o1;
    }

    // tail: re-zero this block's scratch slice (pure stores)
    {
        const float4 z = make_float4(0.f, 0.f, 0.f, 0.f);
        float4* gp4 = reinterpret_cast<float4*>(g_pooled) + (size_t)s0 * 32;
        #pragma unroll
        for (int j = 0; j < 16; ++j)
            gp4[tid + j * GT] = z;
        if (tid < SEGB / 4)
            reinterpret_cast<float4*>(g_denom + s0)[tid] = z;
    }
}

// ---------------------------------------------------------------------------
// Launch (2 kernels). Inputs: x, index, weights, gate_w, gate_b, msg_w,
// msg_b, pow_p. Output: [16384,128] f32.
// ---------------------------------------------------------------------------
extern "C" void kernel_launch(void* const* d_in, const int* in_sizes, int n_in,
                              void* d_out, int out_size)
{
    const float* x       = (const float*)d_in[0];
    const int*   index   = (const int*)  d_in[1];
    const float* weights = (const float*)d_in[2];
    const float* gate_w  = (const float*)d_in[3];
    const float* gate_b  = (const float*)d_in[4];
    const float* msg_w   = (const float*)d_in[5];
    const float* msg_b   = (const float*)d_in[6];
    const float* pow_p   = (const float*)d_in[7];
    float* out = (float*)d_out;

    const int n_rows = in_sizes[1];

    // 1) fused gate + pooling (scratch zeroed by previous call's epilogue,
    //    or by static zero-init on the very first call)
    {
        const int n_warps  = (n_rows + RPW - 1) / RPW;
        const int n_blocks = (n_warps + 7) / 8;             // 8 warps / block
        gate_pool_kernel<<<n_blocks, 256>>>(
            (const float4*)x, index, weights, gate_w, gate_b, pow_p, n_rows);
    }

    // 2) smem-blocked GEMM epilogue + scratch re-zero
    out_gemm_kernel<<<NSEG / SEGB, GT>>>(msg_w, msg_b, out);
}

// round 16
// speedup vs baseline: 1.1100x; 1.1100x over previous
#include <cuda_runtime.h>

#define NSEG 16384
#define DFEAT 128
#define EPSV 1e-10f
#define RPW 64                  // rows per warp (pool kernel)
#define RB 8                    // row batch (ILP depth)
#define SEGB 32                 // segments per block (gemm kernel)
#define KP 32                   // k-panel rows (gemm kernel)
#define GT 256                  // gemm threads per block

// Scratch (allocation-free requirement -> __device__ globals).
// Zero-initialized at module load; out_gemm_kernel re-zeros its own slice
// (pure stores, after compute) so every call sees zeroed scratch.
__device__ float g_pooled[NSEG * DFEAT];   // 8 MB
__device__ float g_denom[NSEG];

__device__ __forceinline__ float4 ldcs4(const float4* p) {
    return __ldcs(p);           // evict-first streaming load
}

// ---------------------------------------------------------------------------
// Kernel 1: fused gate + weighted segment pooling (frozen; ~7 TB/s).
// ---------------------------------------------------------------------------
__global__ void __launch_bounds__(256) gate_pool_kernel(
    const float4* __restrict__ x4,        // [N, 32] float4 view of [N,128]
    const int*    __restrict__ index,     // [N] sorted
    const float*  __restrict__ weights,   // [N]
    const float*  __restrict__ gate_w,    // [128]
    const float*  __restrict__ gate_b,    // [1]
    const float*  __restrict__ pow_p,     // [1]
    int n_rows)
{
    const int lane = threadIdx.x & 31;
    const int warp_global = (blockIdx.x * blockDim.x + threadIdx.x) >> 5;
    const int row0 = warp_global * RPW;
    if (row0 >= n_rows) return;
    const int row_end = min(n_rows, row0 + RPW);

    const float4 gw = reinterpret_cast<const float4*>(gate_w)[lane];
    const float gb = __ldg(gate_b);
    const float p  = __ldg(pow_p);

    const int jmine = 4 * ((lane >> 2) & 1) + 2 * ((lane >> 3) & 1) + ((lane >> 4) & 1);
    const int SRC[RB] = {0, 16, 8, 24, 4, 20, 12, 28};

    float4 acc = make_float4(0.f, 0.f, 0.f, 0.f);
    float dsum = 0.f;
    int cur = __ldg(&index[row0]);

    auto flush = [&]() {
        float* dst = &g_pooled[cur * DFEAT + lane * 4];
        atomicAdd(dst + 0, acc.x);
        atomicAdd(dst + 1, acc.y);
        atomicAdd(dst + 2, acc.z);
        atomicAdd(dst + 3, acc.w);
        if (lane == 0) atomicAdd(&g_denom[cur], dsum);
        acc = make_float4(0.f, 0.f, 0.f, 0.f);
        dsum = 0.f;
    };

    int r = row0;
    for (; r + RB <= row_end; r += RB) {
        float4 xv[RB];
        #pragma unroll
        for (int j = 0; j < RB; ++j)
            xv[j] = ldcs4(&x4[(size_t)(r + j) * 32 + lane]);
        const int segLast = __ldg(&index[r + RB - 1]);
        const float wmine = __ldg(&weights[r + jmine]);

        float pt[RB];
        #pragma unroll
        for (int j = 0; j < RB; ++j)
            pt[j] = xv[j].x * gw.x + xv[j].y * gw.y
                  + xv[j].z * gw.z + xv[j].w * gw.w;

        float q[4];
        #pragma unroll
        for (int k = 0; k < 4; ++k) {
            const float t0 = pt[2 * k]     + __shfl_xor_sync(0xffffffffu, pt[2 * k], 16);
            const float t1 = pt[2 * k + 1] + __shfl_xor_sync(0xffffffffu, pt[2 * k + 1], 16);
            q[k] = (lane & 16) ? t1 : t0;
        }
        float rr2[2];
        #pragma unroll
        for (int m = 0; m < 2; ++m) {
            const float t0 = q[2 * m]     + __shfl_xor_sync(0xffffffffu, q[2 * m], 8);
            const float t1 = q[2 * m + 1] + __shfl_xor_sync(0xffffffffu, q[2 * m + 1], 8);
            rr2[m] = (lane & 8) ? t1 : t0;
        }
        float s;
        {
            const float t0 = rr2[0] + __shfl_xor_sync(0xffffffffu, rr2[0], 4);
            const float t1 = rr2[1] + __shfl_xor_sync(0xffffffffu, rr2[1], 4);
            s = (lane & 4) ? t1 : t0;
        }
        s += __shfl_xor_sync(0xffffffffu, s, 2);
        s += __shfl_xor_sync(0xffffffffu, s, 1);

        const float emine = __expf(__fmaf_rn(p, __logf(wmine), s + gb));

        float e[RB];
        #pragma unroll
        for (int j = 0; j < RB; ++j)
            e[j] = __shfl_sync(0xffffffffu, emine, SRC[j]);

        if (segLast == cur) {
            #pragma unroll
            for (int j = 0; j < RB; ++j) {
                acc.x += e[j] * xv[j].x;
                acc.y += e[j] * xv[j].y;
                acc.z += e[j] * xv[j].z;
                acc.w += e[j] * xv[j].w;
                dsum  += e[j];
            }
        } else {
            #pragma unroll
            for (int j = 0; j < RB; ++j) {
                const int seg = __ldg(&index[r + j]);
                if (seg != cur) { flush(); cur = seg; }
                acc.x += e[j] * xv[j].x;
                acc.y += e[j] * xv[j].y;
                acc.z += e[j] * xv[j].z;
                acc.w += e[j] * xv[j].w;
                dsum  += e[j];
            }
        }
    }
    for (; r < row_end; ++r) {
        const int seg = __ldg(&index[r]);
        const float4 xv = ldcs4(&x4[(size_t)r * 32 + lane]);
        const float w = __ldg(&weights[r]);
        float part = xv.x * gw.x + xv.y * gw.y + xv.z * gw.z + xv.w * gw.w;
        #pragma unroll
        for (int off = 16; off; off >>= 1)
            part += __shfl_xor_sync(0xffffffffu, part, off);
        const float e = __expf(__fmaf_rn(p, __logf(w), part + gb));
        if (seg != cur) { flush(); cur = seg; }
        acc.x += e * xv.x;
        acc.y += e * xv.y;
        acc.z += e * xv.z;
        acc.w += e * xv.w;
        dsum += e;
    }
    flush();
}

// ---------------------------------------------------------------------------
// Kernel 2: smem-blocked GEMM epilogue (R13 shape, tightened).
// 4-seg x 4-col register tile (proven 64-reg shape; R15's 8x8 tile crashed
// occupancy to 10%). Changes vs R13/R14:
//  - KP 64->32: smem 48KB->32KB so the 4-block register limit binds (occ 50%)
//  - __launch_bounds__(256,4): pin regs <= 64
//  - raw accumulation; normalization deferred to epilogue (inv[s] per thread)
// Tail re-zeros this block's scratch slice (pure stores).
// ---------------------------------------------------------------------------
__global__ void __launch_bounds__(GT, 4) out_gemm_kernel(
    const float* __restrict__ msg_w,      // [128,128] row-major (k, n)
    const float* __restrict__ msg_b,      // [128]
    float*       __restrict__ out)        // [NSEG,128]
{
    __shared__ float pr[SEGB][DFEAT];     // 16 KB (RAW pooled rows)
    __shared__ float mw[KP][DFEAT];       // 16 KB (k-panel; row 0 = den scratch)

    const int s0 = blockIdx.x * SEGB;
    const int tid = threadIdx.x;
    const int cg = tid & 31;              // 4 cols at cg*4
    const int sg = tid >> 5;              // 4 segs at sg*4

    // stage 1: den -> mw[0][0..31]
    if (tid < SEGB) mw[0][tid] = g_denom[s0 + tid];
    __syncthreads();

    // per-thread inv + bias gain for my 4 segments (registers, before reuse)
    float inv[4], gbias[4];
    #pragma unroll
    for (int i = 0; i < 4; ++i) {
        const float den = mw[0][sg * 4 + i];
        inv[i]   = __frcp_rn(den + EPSV);
        gbias[i] = den * inv[i];
    }

    // stage 2: raw copy pooled -> pr (1024 float4, 4 per thread)
    {
        const float4* gp4 = reinterpret_cast<const float4*>(g_pooled) + (size_t)s0 * 32;
        #pragma unroll
        for (int j = 0; j < 4; ++j) {
            const int idx = tid + j * GT;           // 0..1023
            *reinterpret_cast<float4*>(&pr[idx >> 5][(idx & 31) * 4]) = gp4[idx];
        }
    }

    float4 acc[4] = {
        make_float4(0.f, 0.f, 0.f, 0.f), make_float4(0.f, 0.f, 0.f, 0.f),
        make_float4(0.f, 0.f, 0.f, 0.f), make_float4(0.f, 0.f, 0.f, 0.f)};

    #pragma unroll
    for (int pnl = 0; pnl < DFEAT / KP; ++pnl) {
        __syncthreads();   // pr built / previous panel consumed / den scratch done
        // load k-panel: 32x128 floats = 1024 float4, 4 per thread, coalesced
        {
            const float4* src = reinterpret_cast<const float4*>(msg_w) + pnl * KP * 32;
            #pragma unroll
            for (int j = 0; j < 4; ++j) {
                const int idx = tid + j * GT;       // 0..1023
                *reinterpret_cast<float4*>(&mw[idx >> 5][(idx & 31) * 4]) = src[idx];
            }
        }
        __syncthreads();

        // compute: k in steps of 4; 4 segs x 4 cols per thread
        #pragma unroll
        for (int kk = 0; kk < KP; kk += 4) {
            float4 m[4];
            #pragma unroll
            for (int t = 0; t < 4; ++t)
                m[t] = *reinterpret_cast<const float4*>(&mw[kk + t][cg * 4]);
            const int k = pnl * KP + kk;
            #pragma unroll
            for (int i = 0; i < 4; ++i) {
                const float4 pv = *reinterpret_cast<const float4*>(&pr[sg * 4 + i][k]);
                acc[i].x += pv.x * m[0].x; acc[i].y += pv.x * m[0].y;
                acc[i].z += pv.x * m[0].z; acc[i].w += pv.x * m[0].w;
                acc[i].x += pv.y * m[1].x; acc[i].y += pv.y * m[1].y;
                acc[i].z += pv.y * m[1].z; acc[i].w += pv.y * m[1].w;
                acc[i].x += pv.z * m[2].x; acc[i].y += pv.z * m[2].y;
                acc[i].z += pv.z * m[2].z; acc[i].w += pv.z * m[2].w;
                acc[i].x += pv.w * m[3].x; acc[i].y += pv.w * m[3].y;
                acc[i].z += pv.w * m[3].z; acc[i].w += pv.w * m[3].w;
            }
        }
    }

    // epilogue: out = inv*acc + gbias*msg_b
    const float4 mb = reinterpret_cast<const float4*>(msg_b)[cg];
    #pragma unroll
    for (int i = 0; i < 4; ++i) {
        const int seg = s0 + sg * 4 + i;
        float4 o = make_float4(inv[i] * acc[i].x + gbias[i] * mb.x,
                               inv[i] * acc[i].y + gbias[i] * mb.y,
                               inv[i] * acc[i].z + gbias[i] * mb.z,
                               inv[i] * acc[i].w + gbias[i] * mb.w);
        reinterpret_cast<float4*>(out)[(size_t)seg * 32 + cg] = o;
    }

    // tail: re-zero this block's scratch slice (pure stores)
    {
        const float4 z = make_float4(0.f, 0.f, 0.f, 0.f);
        float4* gp4 = reinterpret_cast<float4*>(g_pooled) + (size_t)s0 * 32;
        #pragma unroll
        for (int j = 0; j < 4; ++j)
            gp4[tid + j * GT] = z;
        if (tid < SEGB / 4)
            reinterpret_cast<float4*>(g_denom + s0)[tid] = z;
    }
}

// ---------------------------------------------------------------------------
// Launch (2 kernels). Inputs: x, index, weights, gate_w, gate_b, msg_w,
// msg_b, pow_p. Output: [16384,128] f32.
// ---------------------------------------------------------------------------
extern "C" void kernel_launch(void* const* d_in, const int* in_sizes, int n_in,
                              void* d_out, int out_size)
{
    const float* x       = (const float*)d_in[0];
    const int*   index   = (const int*)  d_in[1];
    const float* weights = (const float*)d_in[2];
    const float* gate_w  = (const float*)d_in[3];
    const float* gate_b  = (const float*)d_in[4];
    const float* msg_w   = (const float*)d_in[5];
    const float* msg_b   = (const float*)d_in[6];
    const float* pow_p   = (const float*)d_in[7];
    float* out = (float*)d_out;

    const int n_rows = in_sizes[1];

    // 1) fused gate + pooling (scratch zeroed by previous call's epilogue,
    //    or by static zero-init on the very first call)
    {
        const int n_warps  = (n_rows + RPW - 1) / RPW;
        const int n_blocks = (n_warps + 7) / 8;             // 8 warps / block
        gate_pool_kernel<<<n_blocks, 256>>>(
            (const float4*)x, index, weights, gate_w, gate_b, pow_p, n_rows);
    }

    // 2) smem-blocked GEMM epilogue + scratch re-zero
    out_gemm_kernel<<<NSEG / SEGB, GT>>>(msg_w, msg_b, out);
}